// round 10
// baseline (speedup 1.0000x reference)
#include <cuda_runtime.h>
#include <cuda_bf16.h>
#include <math.h>

// Problem constants (fixed by the dataset)
#define BMAX 1024
#define EMAX 32768
#define CC   64
#define DD   64

// Scratch (static device globals — no allocation allowed)
__device__ long long g_offsets[BMAX + 1];
__device__ int       g_edge_user[EMAX];
__device__ float     g_M1t[DD * DD];     // [j][d] : self part of Wb^T Wf
__device__ float     g_M2t[DD * DD];     // [j][d] : friend part
__device__ float     g_vself[BMAX * DD];
__device__ float     g_v[(size_t)EMAX * DD];

// ---------------------------------------------------------------------------
// Kernel 1: dtype-robust prefix-scan of counts, fill edge->user map.
// ---------------------------------------------------------------------------
__global__ void setup_kernel(const void* __restrict__ counts_raw, int B, int E) {
    __shared__ long long s[BMAX];
    __shared__ int use64;
    int t = threadIdx.x;

    const long long* c64 = (const long long*)counts_raw;
    const int*       c32 = (const int*)counts_raw;

    long long v64 = (t < B) ? c64[t] : 0;
    s[t] = v64;
    __syncthreads();
    for (int o = BMAX >> 1; o > 0; o >>= 1) {
        if (t < o) s[t] += s[t + o];
        __syncthreads();
    }
    if (t == 0) use64 = (s[0] == (long long)E) ? 1 : 0;
    __syncthreads();
    int u64 = use64;
    __syncthreads();

    long long c = 0;
    if (t < B) c = u64 ? c64[t] : (long long)c32[t];
    if (c < 0) c = 0;
    if (c > (long long)EMAX) c = EMAX;

    s[t] = c;
    __syncthreads();
    for (int o = 1; o < BMAX; o <<= 1) {
        long long add = (t >= o) ? s[t - o] : 0;
        __syncthreads();
        s[t] += add;
        __syncthreads();
    }
    if (t == 0) g_offsets[0] = 0;
    if (t < B) g_offsets[t + 1] = s[t];
    long long off = s[t] - c;
    if (t < B) {
        for (long long i = 0; i < c; i++) {
            long long idx = off + i;
            if (idx >= 0 && idx < (long long)EMAX) g_edge_user[idx] = t;
        }
    }
}

// ---------------------------------------------------------------------------
// Kernel 2: M1t[j][d] = sum_f Wb[f][d] * Wf[f][j]
//           M2t[j][d] = sum_f Wb[f][d] * Wf[f][64+j]
// ---------------------------------------------------------------------------
__global__ void mfold_kernel(const float* __restrict__ Wf,
                             const float* __restrict__ Wb) {
    int idx = blockIdx.x * blockDim.x + threadIdx.x;
    if (idx >= 2 * DD * DD) return;
    int d = idx & 63;
    int j = (idx >> 6) & 63;
    int which = idx >> 12;
    float acc = 0.f;
#pragma unroll 8
    for (int f = 0; f < 64; f++)
        acc = fmaf(Wb[f * 64 + d], Wf[f * 128 + which * 64 + j], acc);
    if (which) g_M2t[j * 64 + d] = acc;
    else       g_M1t[j * 64 + d] = acc;
}

// ---------------------------------------------------------------------------
// Kernel 3: vself[u][d] = sum_j M1t[j][d] * self_x[u][j]
// ---------------------------------------------------------------------------
__global__ void vself_kernel(const float* __restrict__ self_x) {
    int u = blockIdx.x, d = threadIdx.x;
    __shared__ float sx[64];
    sx[d] = self_x[u * 64 + d];
    __syncthreads();
    float acc = 0.f;
#pragma unroll 8
    for (int j = 0; j < 64; j++)
        acc = fmaf(g_M1t[j * 64 + d], sx[j], acc);
    g_vself[u * 64 + d] = acc;
}

// ---------------------------------------------------------------------------
// Kernel 4: v[e][d] = vself[u(e)][d] + sum_j M2t[j][d] * friend_x[e][j]
// Register-tiled, 32 edges per block, grid = E/32 = 1024.
// ---------------------------------------------------------------------------
#define FXPAD 68
__global__ __launch_bounds__(256) void vedge_kernel(const float* __restrict__ fx_g) {
    __shared__ float4 M2sh[64 * 16];          // [j][q], 16 KB
    __shared__ float  fxs[32 * FXPAD];        // 32 edges, padded rows (8.5 KB)
    int t = threadIdx.x;

    const float4* M2g = (const float4*)g_M2t;
    for (int i = t; i < 1024; i += 256) M2sh[i] = M2g[i];

    int e0 = blockIdx.x * 32;
    for (int i = t; i < 512; i += 256) {
        int ee = i >> 4, qq = i & 15;
        float4 f = ((const float4*)(fx_g + (size_t)(e0 + ee) * 64))[qq];
        *((float4*)(fxs + ee * FXPAD + qq * 4)) = f;
    }
    __syncthreads();

    int q = t & 15;
    int r = t >> 4;
    int ea = e0 + 2 * r, eb = ea + 1;
    int ua = g_edge_user[ea], ub = g_edge_user[eb];
    float4 acc0 = ((const float4*)(g_vself + (size_t)ua * 64))[q];
    float4 acc1 = ((const float4*)(g_vself + (size_t)ub * 64))[q];
    const float* fa = fxs + (2 * r) * FXPAD;
    const float* fb = fxs + (2 * r + 1) * FXPAD;
#pragma unroll 16
    for (int j = 0; j < 64; j++) {
        float4 m = M2sh[j * 16 + q];
        float a = fa[j], b = fb[j];
        acc0.x = fmaf(m.x, a, acc0.x);
        acc0.y = fmaf(m.y, a, acc0.y);
        acc0.z = fmaf(m.z, a, acc0.z);
        acc0.w = fmaf(m.w, a, acc0.w);
        acc1.x = fmaf(m.x, b, acc1.x);
        acc1.y = fmaf(m.y, b, acc1.y);
        acc1.z = fmaf(m.z, b, acc1.z);
        acc1.w = fmaf(m.w, b, acc1.w);
    }
    ((float4*)(g_v + (size_t)ea * 64))[q] = acc0;
    ((float4*)(g_v + (size_t)eb * 64))[q] = acc1;
}

// ---------------------------------------------------------------------------
// Kernel 5 (main, v3): COALESCED. One warp per edge. Lane l: chunk h=l&15
// (16B of the row), side=l>>4 (row parity). Each LDG.128 covers 2 consecutive
// rows = 512B contiguous = 4 wavefronts (minimum), vs 32 in the thread-per-row
// layout. Mask-gated per half-warp, still skips DRAM lines for masked rows.
// ---------------------------------------------------------------------------
__global__ __launch_bounds__(256)
void main_kernel(const float* __restrict__ common_x,
                 const float* __restrict__ common_time,
                 const int*   __restrict__ common_src_mask,
                 float* __restrict__ out, int max_n, long long out_elems) {
    int warp = threadIdx.x >> 5;   // 0..7
    int lane = threadIdx.x & 31;
    int e = blockIdx.x * 8 + warp;
    int h = lane & 15;             // chunk within row
    int side = lane >> 4;          // row parity within group

    // per-lane v chunk (same for both halves), coalesced 256B load
    float4 v4 = *(const float4*)(g_v + (size_t)e * 64 + h * 4);

    const float* base = common_x + (size_t)e * 64 * 64;
    const int*   mrow = common_src_mask + (size_t)e * 64;
    const float* trow = common_time + (size_t)e * 64;

    float wacc = 0.f;
#pragma unroll 4
    for (int g = 0; g < 32; g++) {
        int row = g * 2 + side;
        int mk = mrow[row];                       // broadcast per half-warp
        float partial = 0.f;
        if (mk != 0) {
            float4 x = *(const float4*)(base + row * 64 + h * 4);
            partial = fmaf(x.x, v4.x, fmaf(x.y, v4.y,
                      fmaf(x.z, v4.z, x.w * v4.w)));
        }
        // reduce the 16 chunk-lanes of each row (xor<=8 stays in half)
        partial += __shfl_xor_sync(0xffffffffu, partial, 8);
        partial += __shfl_xor_sync(0xffffffffu, partial, 4);
        partial += __shfl_xor_sync(0xffffffffu, partial, 2);
        partial += __shfl_xor_sync(0xffffffffu, partial, 1);
        if (h == 0 && mk != 0) {
            float tm = trow[row];
            float sp = fmaxf(partial, 0.f) + log1pf(expf(-fabsf(partial)));
            wacc += sp * expf(fmaf(tm, -1e-6f, 1.0f));
        }
    }
    // combine the two row-parity accumulators (lanes 0 and 16)
    wacc += __shfl_xor_sync(0xffffffffu, wacc, 16);
    if (lane == 0) {
        int u = g_edge_user[e];
        long long oi = (long long)u * max_n + (long long)(e - g_offsets[u]);
        if (oi >= 0 && oi < out_elems)
            out[oi] = wacc;
    }
}

// ---------------------------------------------------------------------------
extern "C" void kernel_launch(void* const* d_in, const int* in_sizes, int n_in,
                              void* d_out, int out_size) {
    const float* self_x      = (const float*)d_in[0];
    const float* common_x    = (const float*)d_in[1];
    const float* common_time = (const float*)d_in[2];
    const int*   src_mask    = (const int*)d_in[3];
    const float* friend_x    = (const float*)d_in[4];
    const void*  counts      = (const void*)d_in[5];
    const float* W_friend    = (const float*)d_in[6];
    const float* W_beta      = (const float*)d_in[7];
    float*       out         = (float*)d_out;

    int B = in_sizes[5];
    int E = in_sizes[4] / 64;
    int max_n = out_size / B;

    setup_kernel<<<1, BMAX>>>(counts, B, E);
    mfold_kernel<<<(2 * DD * DD + 255) / 256, 256>>>(W_friend, W_beta);
    vself_kernel<<<B, 64>>>(self_x);
    vedge_kernel<<<E / 32, 256>>>(friend_x);
    cudaMemsetAsync(d_out, 0, (size_t)out_size * sizeof(float), 0);
    main_kernel<<<E / 8, 256>>>(common_x, common_time, src_mask, out, max_n,
                                (long long)out_size);
}